// round 13
// baseline (speedup 1.0000x reference)
#include <cuda_runtime.h>
#include <cstdint>

// Distral multi-head tiny MLP (N = 32769 heads). Established: L2 persists
// across graph replays; evict_last W1+b1 (52MB) + evict_first W2 = 16.9us.
// Steady state is latency-exposed (~4us), not DRAM-byte-bound (R10/R12 W2-
// protection experiments were neutral). R13: same R9 policies, restructured
// for regs<=32 (compute h BEFORE W2 loads to free W1 registers) and
// __launch_bounds__(256,8) -> 64 warps/SM to shrink the latency exposure.

#define HID 100
#define OUT 5

__device__ __forceinline__ uint64_t pol_keep() {
    uint64_t p;
    asm("createpolicy.fractional.L2::evict_last.b64 %0, 1.0;" : "=l"(p));
    return p;
}
__device__ __forceinline__ uint64_t pol_stream() {
    uint64_t p;
    asm("createpolicy.fractional.L2::evict_first.b64 %0, 1.0;" : "=l"(p));
    return p;
}
__device__ __forceinline__ float4 ldg_hint(const float4* p, uint64_t pol) {
    float4 v;
    asm volatile("ld.global.nc.L2::cache_hint.v4.f32 {%0,%1,%2,%3}, [%4], %5;"
                 : "=f"(v.x), "=f"(v.y), "=f"(v.z), "=f"(v.w)
                 : "l"(p), "l"(pol));
    return v;
}

__global__ __launch_bounds__(256, 8) void distral_kernel(
    const float* __restrict__ x,
    const float* __restrict__ W1,
    const float* __restrict__ b1,
    const float* __restrict__ W2,
    const float* __restrict__ b2,
    float* __restrict__ out,
    int n_heads)
{
    const int lane  = threadIdx.x & 31;
    const int gwarp = (blockIdx.x * blockDim.x + threadIdx.x) >> 5;
    const int nwarp = (gridDim.x * blockDim.x) >> 5;

    const uint64_t pk = pol_keep();    // W1,b1: resident set (52.4MB)
    const uint64_t ps = pol_stream();  // W2: streaming

    // lane l (l<25) owns hidden units j in [4l, 4l+4)
    for (int head = gwarp; head < n_heads; head += nwarp) {
        const float4* g1 = (const float4*)(W1 + (size_t)head * (HID * 3));
        const float4* gb = (const float4*)(b1 + (size_t)head * HID);
        const float4* g2 = (const float4*)(W2 + (size_t)head * (OUT * HID));

        // ---- phase 1: W1/b1/x -> h (W1 registers die here) ----
        float4 w1a, w1b, w1c, b1v;
        if (lane < 25) {
            w1a = ldg_hint(g1 + 3 * lane + 0, pk);
            w1b = ldg_hint(g1 + 3 * lane + 1, pk);
            w1c = ldg_hint(g1 + 3 * lane + 2, pk);
            b1v = ldg_hint(gb + lane, pk);
        } else {
            w1a = w1b = w1c = b1v = make_float4(0.f, 0.f, 0.f, 0.f);
        }
        const float x0 = __ldg(x + (size_t)head * 3 + 0);
        const float x1 = __ldg(x + (size_t)head * 3 + 1);
        const float x2 = __ldg(x + (size_t)head * 3 + 2);

        float h0 = fmaxf(fmaf(w1a.x, x0, fmaf(w1a.y, x1, fmaf(w1a.z, x2, b1v.x))), 0.f);
        float h1 = fmaxf(fmaf(w1a.w, x0, fmaf(w1b.x, x1, fmaf(w1b.y, x2, b1v.y))), 0.f);
        float h2 = fmaxf(fmaf(w1b.z, x0, fmaf(w1b.w, x1, fmaf(w1c.x, x2, b1v.z))), 0.f);
        float h3 = fmaxf(fmaf(w1c.y, x0, fmaf(w1c.z, x1, fmaf(w1c.w, x2, b1v.w))), 0.f);

        // ---- phase 2: W2 rows, dot + butterfly per output ----
        float logits[OUT];
        #pragma unroll
        for (int o = 0; o < OUT; o++) {
            float4 q = (lane < 25) ? ldg_hint(g2 + 25 * o + lane, ps)
                                   : make_float4(0.f, 0.f, 0.f, 0.f);
            float p = fmaf(q.x, h0, fmaf(q.y, h1, fmaf(q.z, h2, q.w * h3)));
            #pragma unroll
            for (int s = 16; s; s >>= 1)
                p += __shfl_xor_sync(0xffffffffu, p, s);
            logits[o] = p + __ldg(b2 + (size_t)head * OUT + o);
        }

        // ---- softmax over 5 ----
        float mx = logits[0];
        #pragma unroll
        for (int o = 1; o < OUT; o++) mx = fmaxf(mx, logits[o]);
        float e[OUT], sum = 0.0f;
        #pragma unroll
        for (int o = 0; o < OUT; o++) { e[o] = __expf(logits[o] - mx); sum += e[o]; }
        float inv = __frcp_rn(sum);

        if (lane < OUT)
            out[(size_t)head * OUT + lane] = e[lane] * inv;
    }
}

extern "C" void kernel_launch(void* const* d_in, const int* in_sizes, int n_in,
                              void* d_out, int out_size)
{
    const float* x  = (const float*)d_in[0];
    const float* W1 = (const float*)d_in[1];
    const float* b1 = (const float*)d_in[2];
    const float* W2 = (const float*)d_in[3];
    const float* b2 = (const float*)d_in[4];
    float* out = (float*)d_out;

    const int n_heads = in_sizes[0] / 3;   // x is (N, 3)

    const int blocks = 148 * 8;            // fill 8 blocks/SM residency
    distral_kernel<<<blocks, 256>>>(x, W1, b1, W2, b2, out, n_heads);
}

// round 14
// speedup vs baseline: 1.0234x; 1.0234x over previous
#include <cuda_runtime.h>
#include <cstdint>

// Distral multi-head tiny MLP (N = 32769 heads). Established across R9-R13:
//   - L2 persists across graph replays; evict_last W1+b1 (52MB) + evict_first
//     W2 -> 16.9us best (R9). More/less reg pressure and more W2 protection
//     all regress or are neutral.
//   - Steady state: W2 streams ~66MB from DRAM, latency-exposed ~4us.
// R14 = R9 + prefetch.global.L2 of the NEXT head's W2 lines (fire-and-forget,
// no regs): at use time next iteration, W2 is an L2 hit instead of DRAM miss.

#define HID 100
#define OUT 5

__device__ __forceinline__ uint64_t pol_keep() {
    uint64_t p;
    asm("createpolicy.fractional.L2::evict_last.b64 %0, 1.0;" : "=l"(p));
    return p;
}
__device__ __forceinline__ uint64_t pol_stream() {
    uint64_t p;
    asm("createpolicy.fractional.L2::evict_first.b64 %0, 1.0;" : "=l"(p));
    return p;
}
__device__ __forceinline__ float4 ldg_hint(const float4* p, uint64_t pol) {
    float4 v;
    asm volatile("ld.global.nc.L2::cache_hint.v4.f32 {%0,%1,%2,%3}, [%4], %5;"
                 : "=f"(v.x), "=f"(v.y), "=f"(v.z), "=f"(v.w)
                 : "l"(p), "l"(pol));
    return v;
}
__device__ __forceinline__ void pf_l2(const void* p) {
    asm volatile("prefetch.global.L2 [%0];" :: "l"(p));
}

__global__ __launch_bounds__(256) void distral_kernel(
    const float* __restrict__ x,
    const float* __restrict__ W1,
    const float* __restrict__ b1,
    const float* __restrict__ W2,
    const float* __restrict__ b2,
    float* __restrict__ out,
    int n_heads)
{
    const int lane  = threadIdx.x & 31;
    const int gwarp = (blockIdx.x * blockDim.x + threadIdx.x) >> 5;
    const int nwarp = (gridDim.x * blockDim.x) >> 5;

    const uint64_t pk = pol_keep();    // W1,b1: resident set (52.4MB)
    const uint64_t ps = pol_stream();  // W2: streaming

    // lane l (l<25) owns hidden units j in [4l, 4l+4)
    for (int head = gwarp; head < n_heads; head += nwarp) {
        const float4* g1 = (const float4*)(W1 + (size_t)head * (HID * 3));
        const float4* gb = (const float4*)(b1 + (size_t)head * HID);
        const float4* g2 = (const float4*)(W2 + (size_t)head * (OUT * HID));

        // ---- batched load burst (proven R9 structure: all 9 wide loads) ----
        float4 w1a, w1b, w1c, b1v, w2v[OUT];
        if (lane < 25) {
            w1a = ldg_hint(g1 + 3 * lane + 0, pk);
            w1b = ldg_hint(g1 + 3 * lane + 1, pk);
            w1c = ldg_hint(g1 + 3 * lane + 2, pk);
            b1v = ldg_hint(gb + lane, pk);
            #pragma unroll
            for (int o = 0; o < OUT; o++) w2v[o] = ldg_hint(g2 + 25 * o + lane, ps);
        } else {
            w1a = w1b = w1c = b1v = make_float4(0.f, 0.f, 0.f, 0.f);
            #pragma unroll
            for (int o = 0; o < OUT; o++) w2v[o] = make_float4(0.f, 0.f, 0.f, 0.f);
        }

        // ---- prefetch NEXT head's W2 into L2 (covers DRAM latency) ----
        {
            const int nxt = head + nwarp;
            if (nxt < n_heads && lane < 25) {
                const float4* g2n = (const float4*)(W2 + (size_t)nxt * (OUT * HID));
                #pragma unroll
                for (int o = 0; o < OUT; o++) pf_l2(g2n + 25 * o + lane);
            }
        }

        const float x0 = __ldg(x + (size_t)head * 3 + 0);
        const float x1 = __ldg(x + (size_t)head * 3 + 1);
        const float x2 = __ldg(x + (size_t)head * 3 + 2);

        const float f[12] = { w1a.x, w1a.y, w1a.z, w1a.w,
                              w1b.x, w1b.y, w1b.z, w1b.w,
                              w1c.x, w1c.y, w1c.z, w1c.w };
        const float bb[4] = { b1v.x, b1v.y, b1v.z, b1v.w };

        float h[4];
        #pragma unroll
        for (int k = 0; k < 4; k++) {
            float v = fmaf(f[3 * k + 0], x0,
                      fmaf(f[3 * k + 1], x1,
                      fmaf(f[3 * k + 2], x2, bb[k])));
            h[k] = fmaxf(v, 0.0f);
        }

        float logits[OUT];
        #pragma unroll
        for (int o = 0; o < OUT; o++) {
            float4 q = w2v[o];
            float p = fmaf(q.x, h[0], fmaf(q.y, h[1], fmaf(q.z, h[2], q.w * h[3])));
            #pragma unroll
            for (int s = 16; s; s >>= 1)
                p += __shfl_xor_sync(0xffffffffu, p, s);
            logits[o] = p + __ldg(b2 + (size_t)head * OUT + o);
        }

        float mx = logits[0];
        #pragma unroll
        for (int o = 1; o < OUT; o++) mx = fmaxf(mx, logits[o]);
        float e[OUT], sum = 0.0f;
        #pragma unroll
        for (int o = 0; o < OUT; o++) { e[o] = __expf(logits[o] - mx); sum += e[o]; }
        float inv = __frcp_rn(sum);

        if (lane < OUT)
            out[(size_t)head * OUT + lane] = e[lane] * inv;
    }
}

extern "C" void kernel_launch(void* const* d_in, const int* in_sizes, int n_in,
                              void* d_out, int out_size)
{
    const float* x  = (const float*)d_in[0];
    const float* W1 = (const float*)d_in[1];
    const float* b1 = (const float*)d_in[2];
    const float* W2 = (const float*)d_in[3];
    const float* b2 = (const float*)d_in[4];
    float* out = (float*)d_out;

    const int n_heads = in_sizes[0] / 3;   // x is (N, 3)

    const int blocks = 148 * 6;            // R9's proven residency (regs ~40)
    distral_kernel<<<blocks, 256>>>(x, W1, b1, W2, b2, out, n_heads);
}

// round 15
// speedup vs baseline: 1.2239x; 1.1959x over previous
#include <cuda_runtime.h>
#include <cstdint>

// Distral multi-head tiny MLP (N = 32769 heads). Established: L2 persists
// across graph replays; DETERMINISTIC (fraction=1.0) evict_last on a stable
// range retains; fractional policies don't (random subset per replay -> R10/
// R12 neutral). R9 (protect W1+b1=52MB) = 16.9us with steady DRAM ~68MB.
// R15 swaps the resident set: protect W2 FULLY (65.5MB, 52% of L2, evict_last)
// and stream W1+b1 (evict_first). Steady DRAM -> ~54MB. Kernel body = R9.

#define HID 100
#define OUT 5

__device__ __forceinline__ uint64_t pol_keep() {
    uint64_t p;
    asm("createpolicy.fractional.L2::evict_last.b64 %0, 1.0;" : "=l"(p));
    return p;
}
__device__ __forceinline__ uint64_t pol_stream() {
    uint64_t p;
    asm("createpolicy.fractional.L2::evict_first.b64 %0, 1.0;" : "=l"(p));
    return p;
}
__device__ __forceinline__ float4 ldg_hint(const float4* p, uint64_t pol) {
    float4 v;
    asm volatile("ld.global.nc.L2::cache_hint.v4.f32 {%0,%1,%2,%3}, [%4], %5;"
                 : "=f"(v.x), "=f"(v.y), "=f"(v.z), "=f"(v.w)
                 : "l"(p), "l"(pol));
    return v;
}

__global__ __launch_bounds__(256) void distral_kernel(
    const float* __restrict__ x,
    const float* __restrict__ W1,
    const float* __restrict__ b1,
    const float* __restrict__ W2,
    const float* __restrict__ b2,
    float* __restrict__ out,
    int n_heads)
{
    const int lane  = threadIdx.x & 31;
    const int gwarp = (blockIdx.x * blockDim.x + threadIdx.x) >> 5;
    const int nwarp = (gridDim.x * blockDim.x) >> 5;

    const uint64_t pk = pol_keep();    // W2: resident set (65.5MB, deterministic)
    const uint64_t ps = pol_stream();  // W1, b1: streaming

    // lane l (l<25) owns hidden units j in [4l, 4l+4)
    for (int head = gwarp; head < n_heads; head += nwarp) {
        const float4* g1 = (const float4*)(W1 + (size_t)head * (HID * 3));
        const float4* gb = (const float4*)(b1 + (size_t)head * HID);
        const float4* g2 = (const float4*)(W2 + (size_t)head * (OUT * HID));

        // batched load burst (proven R9 structure: all 9 wide loads up front)
        float4 w1a, w1b, w1c, b1v, w2v[OUT];
        if (lane < 25) {
            w1a = ldg_hint(g1 + 3 * lane + 0, ps);
            w1b = ldg_hint(g1 + 3 * lane + 1, ps);
            w1c = ldg_hint(g1 + 3 * lane + 2, ps);
            b1v = ldg_hint(gb + lane, ps);
            #pragma unroll
            for (int o = 0; o < OUT; o++) w2v[o] = ldg_hint(g2 + 25 * o + lane, pk);
        } else {
            w1a = w1b = w1c = b1v = make_float4(0.f, 0.f, 0.f, 0.f);
            #pragma unroll
            for (int o = 0; o < OUT; o++) w2v[o] = make_float4(0.f, 0.f, 0.f, 0.f);
        }

        const float x0 = __ldg(x + (size_t)head * 3 + 0);
        const float x1 = __ldg(x + (size_t)head * 3 + 1);
        const float x2 = __ldg(x + (size_t)head * 3 + 2);

        const float f[12] = { w1a.x, w1a.y, w1a.z, w1a.w,
                              w1b.x, w1b.y, w1b.z, w1b.w,
                              w1c.x, w1c.y, w1c.z, w1c.w };
        const float bb[4] = { b1v.x, b1v.y, b1v.z, b1v.w };

        float h[4];
        #pragma unroll
        for (int k = 0; k < 4; k++) {
            float v = fmaf(f[3 * k + 0], x0,
                      fmaf(f[3 * k + 1], x1,
                      fmaf(f[3 * k + 2], x2, bb[k])));
            h[k] = fmaxf(v, 0.0f);
        }

        float logits[OUT];
        #pragma unroll
        for (int o = 0; o < OUT; o++) {
            float4 q = w2v[o];
            float p = fmaf(q.x, h[0], fmaf(q.y, h[1], fmaf(q.z, h[2], q.w * h[3])));
            #pragma unroll
            for (int s = 16; s; s >>= 1)
                p += __shfl_xor_sync(0xffffffffu, p, s);
            logits[o] = p + __ldg(b2 + (size_t)head * OUT + o);
        }

        float mx = logits[0];
        #pragma unroll
        for (int o = 1; o < OUT; o++) mx = fmaxf(mx, logits[o]);
        float e[OUT], sum = 0.0f;
        #pragma unroll
        for (int o = 0; o < OUT; o++) { e[o] = __expf(logits[o] - mx); sum += e[o]; }
        float inv = __frcp_rn(sum);

        if (lane < OUT)
            out[(size_t)head * OUT + lane] = e[lane] * inv;
    }
}

extern "C" void kernel_launch(void* const* d_in, const int* in_sizes, int n_in,
                              void* d_out, int out_size)
{
    const float* x  = (const float*)d_in[0];
    const float* W1 = (const float*)d_in[1];
    const float* b1 = (const float*)d_in[2];
    const float* W2 = (const float*)d_in[3];
    const float* b2 = (const float*)d_in[4];
    float* out = (float*)d_out;

    const int n_heads = in_sizes[0] / 3;   // x is (N, 3)

    const int blocks = 148 * 6;            // R9's proven residency (regs ~40)
    distral_kernel<<<blocks, 256>>>(x, W1, b1, W2, b2, out, n_heads);
}